// round 2
// baseline (speedup 1.0000x reference)
#include <cuda_runtime.h>
#include <math.h>

#define Bq 4
#define Nq 2048
#define Kq 48
#define EC 128

// Scratch: gathered/masked token center coords, [B*N] as float4
__device__ float4 g_X[Bq * Nq];

__device__ __forceinline__ unsigned long long pack2(float a, float b) {
    unsigned long long r;
    asm("mov.b64 %0, {%1, %2};" : "=l"(r) : "f"(a), "f"(b));
    return r;
}
__device__ __forceinline__ void unpack2(unsigned long long v, float& a, float& b) {
    asm("mov.b64 {%0, %1}, %2;" : "=f"(a), "=f"(b) : "l"(v));
}
__device__ __forceinline__ void fma2(unsigned long long& d, unsigned long long a,
                                     unsigned long long b) {
    asm("fma.rn.f32x2 %0, %1, %2, %3;" : "=l"(d) : "l"(a), "l"(b), "l"(d));
}

// ---------------------------------------------------------------------------
// Kernel 1: gather center-atom coords, apply token mask
// ---------------------------------------------------------------------------
__global__ void gather_x_kernel(const float* __restrict__ coords,
                                const float* __restrict__ mask,
                                const int* __restrict__ center) {
    int t = blockIdx.x * blockDim.x + threadIdx.x;
    if (t >= Bq * Nq) return;
    int b = t / Nq;
    int c = center[t];
    float m = mask[t];
    const float* p = coords + ((size_t)b * Nq + c) * 3;
    g_X[t] = make_float4(p[0] * m, p[1] * m, p[2] * m, 0.f);
}

// ---------------------------------------------------------------------------
// Kernel 2: masked pairwise distances + exact top-K (smallest, jax tie order)
// via 4-round radix-select (11-bit digits) over u64 keys
// (float_bits(D_adjust)<<32 | j). Warp-aggregated histogram (match_any) to
// avoid same-address smem-atomic serialization on clustered exponents.
// ---------------------------------------------------------------------------
__global__ __launch_bounds__(256) void knn_kernel(const float* __restrict__ mask,
                                                  float* __restrict__ outIdx,
                                                  float* __restrict__ outD) {
    __shared__ float Dsm[Nq];
    __shared__ unsigned int hist[2048];
    __shared__ float warpred[8];
    __shared__ unsigned scanw[8];
    __shared__ unsigned scanoff[8];
    __shared__ float s_Dmax;
    __shared__ unsigned s_digit;
    __shared__ int s_rank;
    __shared__ unsigned long long cand[Kq];
    __shared__ int s_cnt;

    int row = blockIdx.x;
    int b = row / Nq;
    int tid = threadIdx.x;
    int lane = tid & 31, warp = tid >> 5;

    float4 xi = g_X[row];
    float mi = mask[row];
    const float* mrow = mask + b * Nq;

    // Pass 1: distances + row max
    float lmax = 0.f;
#pragma unroll
    for (int q = 0; q < Nq / 256; q++) {
        int j = tid + q * 256;
        float4 xj = g_X[b * Nq + j];
        float dx = xi.x - xj.x, dy = xi.y - xj.y, dz = xi.z - xj.z;
        float d = mi * mrow[j] * sqrtf(dx * dx + dy * dy + dz * dz + 1e-6f);
        Dsm[j] = d;
        lmax = fmaxf(lmax, d);
    }
    for (int o = 16; o; o >>= 1) lmax = fmaxf(lmax, __shfl_xor_sync(~0u, lmax, o));
    if (lane == 0) warpred[warp] = lmax;
    __syncthreads();
    if (tid == 0) {
        float m = warpred[0];
#pragma unroll
        for (int w = 1; w < 8; w++) m = fmaxf(m, warpred[w]);
        s_Dmax = m;
        s_rank = Kq;
        s_cnt = 0;
    }
    __syncthreads();
    float Dmax = s_Dmax;

    // Pass 2: u64 keys in registers (D_adjust bits << 32 | index)
    unsigned long long kreg[Nq / 256];
#pragma unroll
    for (int q = 0; q < Nq / 256; q++) {
        int j = tid + q * 256;
        float m2 = mi * mrow[j];
        float adj = Dsm[j] + (1.f - m2) * Dmax;
        kreg[q] = ((unsigned long long)__float_as_uint(adj) << 32) | (unsigned)j;
    }

    // 4-round radix select: digits at shifts {53,42,32,0} with widths
    // {11,11,10,11} bits. Bits 31:11 of every key are zero (j < 2048).
    const int shifts[4] = {53, 42, 32, 0};
    const unsigned dmasks[4] = {0x7FFu, 0x7FFu, 0x3FFu, 0x7FFu};
    unsigned long long prefix = 0, pmask = 0;
#pragma unroll 1
    for (int r = 0; r < 4; r++) {
        int sh = shifts[r];
        unsigned dmask = dmasks[r];
        // clear hist
#pragma unroll
        for (int q = 0; q < 8; q++) hist[tid + q * 256] = 0;
        __syncthreads();
        // warp-aggregated histogram
#pragma unroll
        for (int q = 0; q < Nq / 256; q++) {
            bool act = (kreg[q] & pmask) == prefix;
            unsigned d = act ? (unsigned)((kreg[q] >> sh) & dmask) : 0xFFFFFFFFu;
            unsigned mm = __match_any_sync(0xFFFFFFFFu, d);
            int leader = __ffs(mm) - 1;
            if (act && lane == leader) atomicAdd(&hist[d], (unsigned)__popc(mm));
        }
        __syncthreads();
        // block scan over 2048 bins (8 per thread)
        unsigned binv[8];
        unsigned p = 0;
#pragma unroll
        for (int q = 0; q < 8; q++) { binv[q] = hist[tid * 8 + q]; p += binv[q]; }
        unsigned incl = p;
        for (int o = 1; o < 32; o <<= 1) {
            unsigned v = __shfl_up_sync(~0u, incl, o);
            if (lane >= o) incl += v;
        }
        if (lane == 31) scanw[warp] = incl;
        __syncthreads();
        if (tid == 0) {
            unsigned acc = 0;
#pragma unroll
            for (int w = 0; w < 8; w++) { unsigned t = scanw[w]; scanoff[w] = acc; acc += t; }
        }
        int rk = s_rank;  // read before any write this round
        __syncthreads();
        unsigned excl = incl - p + scanoff[warp];
        if ((int)excl < rk && rk <= (int)(excl + p)) {
            int rr = rk - (int)excl;
#pragma unroll
            for (int q = 0; q < 8; q++) {
                if (rr <= (int)binv[q]) { s_digit = tid * 8 + q; s_rank = rr; break; }
                rr -= (int)binv[q];
            }
        }
        __syncthreads();
        prefix |= ((unsigned long long)s_digit) << sh;
        pmask |= ((unsigned long long)dmask) << sh;
    }
    // prefix == exact Kq-th smallest key; gather all keys <= prefix (exactly Kq)
#pragma unroll
    for (int q = 0; q < Nq / 256; q++)
        if (kreg[q] <= prefix) {
            int pos = atomicAdd(&s_cnt, 1);
            if (pos < Kq) cand[pos] = kreg[q];
        }
    __syncthreads();
    if (tid < Kq) {
        unsigned long long k = cand[tid];
        int rk = 0;
#pragma unroll
        for (int s = 0; s < Kq; s++) rk += (cand[s] < k);
        int j = (int)(unsigned)(k & 0xFFFFFFFFull);
        outIdx[(size_t)row * Kq + rk] = (float)j;
        outD[(size_t)row * Kq + rk] = __uint_as_float((unsigned)(k >> 32));
    }
}

// ---------------------------------------------------------------------------
// Kernel 3: edge features [48 x 33] -> GEMM with edge_w [33 x 128] -> LayerNorm
// 64 threads per (b,i); thread owns channel pair (c, c+64); packed f32x2 FMA.
// Features stored duplicated (f,f) in smem so LDS.128 yields packed operands.
// ---------------------------------------------------------------------------
__global__ __launch_bounds__(64) void edge_kernel(
    const float* __restrict__ eidx, const float* __restrict__ dnb,
    const int* __restrict__ resi, const int* __restrict__ lig,
    const float* __restrict__ bonds,
    const float* __restrict__ pe_w, const float* __restrict__ pe_b,
    const float* __restrict__ edge_w,
    const float* __restrict__ ln_g, const float* __restrict__ ln_b,
    float* __restrict__ outE) {
    __shared__ __align__(16) float2 fd[Kq][36];  // duplicated features, 13.8KB
    __shared__ float red[16][2][2];
    __shared__ float stats[16][2];

    int c = threadIdx.x;  // 0..63
    int lane = c & 31, warp = c >> 5;
    int row = blockIdx.x;
    int b = row / Nq, i = row % Nq;

    // packed weight pairs for channels (c, c+64)
    unsigned long long w2[36];
#pragma unroll
    for (int t = 0; t < 33; t++)
        w2[t] = pack2(edge_w[t * EC + c], edge_w[t * EC + c + 64]);
    w2[33] = w2[34] = w2[35] = 0ull;
    float g0 = ln_g[c], g1 = ln_g[c + 64];
    float b0 = ln_b[c], b1 = ln_b[c + 64];

    int ri = resi[row];
    int li = lig[row];
    const float* brow = bonds + ((size_t)b * Nq + i) * Nq;

    // Build feature rows (threads 0..47, one edge each), duplicated (f,f)
    if (c < Kq) {
        int k = c;
        int j = (int)eidx[(size_t)row * Kq + k];
        float dk = dnb[(size_t)row * Kq + k];
        // chain_labels all-zero in reference => E_chains == 1 always
        int d = ri - resi[b * Nq + j] + 32;
        d = max(0, min(64, d));
#pragma unroll
        for (int t = 0; t < 16; t++) {
            float v = pe_w[d * 16 + t] + pe_b[t];
            fd[k][t] = make_float2(v, v);
        }
#pragma unroll
        for (int m = 0; m < 16; m++) {
            float mu = 2.f + (20.f / 15.f) * (float)m;
            float x = (dk - mu) * 0.8f;  // 1/1.25
            float v = __expf(-x * x);
            fd[k][16 + m] = make_float2(v, v);
        }
        float tb = (li | lig[b * Nq + j]) ? brow[j] : 0.f;
        fd[k][32] = make_float2(tb, tb);
        fd[k][33] = fd[k][34] = fd[k][35] = make_float2(0.f, 0.f);
    }
    __syncthreads();

    for (int k0 = 0; k0 < Kq; k0 += 16) {
        unsigned long long acc[16];
#pragma unroll
        for (int kk = 0; kk < 16; kk++) {
            const ulonglong2* fp = (const ulonglong2*)fd[k0 + kk];
            unsigned long long a = 0ull;
#pragma unroll
            for (int q = 0; q < 18; q++) {
                ulonglong2 v = fp[q];
                fma2(a, v.x, w2[2 * q]);
                fma2(a, v.y, w2[2 * q + 1]);
            }
            acc[kk] = a;
        }
        // LN reductions across 128 channels (2 warps x 2 lanes-per-thread)
#pragma unroll
        for (int kk = 0; kk < 16; kk++) {
            float ex, ey;
            unpack2(acc[kk], ex, ey);
            float s = ex + ey, s2 = ex * ex + ey * ey;
            for (int o = 16; o; o >>= 1) {
                s += __shfl_xor_sync(~0u, s, o);
                s2 += __shfl_xor_sync(~0u, s2, o);
            }
            if (lane == 0) { red[kk][warp][0] = s; red[kk][warp][1] = s2; }
        }
        __syncthreads();
        if (c < 16) {
            float s = red[c][0][0] + red[c][1][0];
            float s2 = red[c][0][1] + red[c][1][1];
            float mean = s * (1.f / EC);
            float var = s2 * (1.f / EC) - mean * mean;
            stats[c][0] = mean;
            stats[c][1] = rsqrtf(var + 1e-5f);
        }
        __syncthreads();
        size_t baseo = ((size_t)row * Kq + k0) * EC + c;
#pragma unroll
        for (int kk = 0; kk < 16; kk++) {
            float mean = stats[kk][0], rstd = stats[kk][1];
            float ex, ey;
            unpack2(acc[kk], ex, ey);
            outE[baseo + (size_t)kk * EC] = (ex - mean) * rstd * g0 + b0;
            outE[baseo + (size_t)kk * EC + 64] = (ey - mean) * rstd * g1 + b1;
        }
        __syncthreads();
    }
}

// ---------------------------------------------------------------------------
extern "C" void kernel_launch(void* const* d_in, const int* in_sizes, int n_in,
                              void* d_out, int out_size) {
    const float* coords = (const float*)d_in[0];
    const float* mask   = (const float*)d_in[1];
    const float* bonds  = (const float*)d_in[2];
    const float* pe_w   = (const float*)d_in[3];
    const float* pe_b   = (const float*)d_in[4];
    const float* edge_w = (const float*)d_in[5];
    const float* ln_g   = (const float*)d_in[6];
    const float* ln_b   = (const float*)d_in[7];
    const int* center   = (const int*)d_in[8];
    const int* resi     = (const int*)d_in[9];
    // d_in[10] = asym_id (unused: chain encoding disabled in reference)
    const int* lig      = (const int*)d_in[11];

    float* outE = (float*)d_out;
    size_t nE = (size_t)Bq * Nq * Kq * EC;        // 50,331,648
    float* outIdx = outE + nE;                    // E_idx as float
    float* outD = outIdx + (size_t)Bq * Nq * Kq;  // D_neighbors

    gather_x_kernel<<<(Bq * Nq + 255) / 256, 256>>>(coords, mask, center);
    knn_kernel<<<Bq * Nq, 256>>>(mask, outIdx, outD);
    edge_kernel<<<Bq * Nq, 64>>>(outIdx, outD, resi, lig, bonds, pe_w, pe_b,
                                 edge_w, ln_g, ln_b, outE);
}

// round 3
// speedup vs baseline: 2.0625x; 2.0625x over previous
#include <cuda_runtime.h>
#include <math.h>

#define Bq 4
#define Nq 2048
#define Kq 48
#define EC 128

// Scratch: gathered/masked token center coords, [B*N] as float4
__device__ float4 g_X[Bq * Nq];
// Precomputed positional-encoding contribution: C[d][c] for d in [0,65]
__device__ float g_C[66 * EC];

// ---------------------------------------------------------------------------
// Kernel 0: fold (one_hot(d) @ pe_w + pe_b) @ edge_w[0:16] into a 66x128 LUT
// ---------------------------------------------------------------------------
__global__ void prep_c_kernel(const float* __restrict__ pe_w,
                              const float* __restrict__ pe_b,
                              const float* __restrict__ edge_w) {
    int d = blockIdx.x;
    int c = threadIdx.x;
    float acc = 0.f;
#pragma unroll
    for (int t = 0; t < 16; t++)
        acc += (pe_w[d * 16 + t] + pe_b[t]) * edge_w[t * EC + c];
    g_C[d * EC + c] = acc;
}

// ---------------------------------------------------------------------------
// Kernel 1: gather center-atom coords, apply token mask
// ---------------------------------------------------------------------------
__global__ void gather_x_kernel(const float* __restrict__ coords,
                                const float* __restrict__ mask,
                                const int* __restrict__ center) {
    int t = blockIdx.x * blockDim.x + threadIdx.x;
    if (t >= Bq * Nq) return;
    int b = t / Nq;
    int c = center[t];
    float m = mask[t];
    const float* p = coords + ((size_t)b * Nq + c) * 3;
    g_X[t] = make_float4(p[0] * m, p[1] * m, p[2] * m, 0.f);
}

// ---------------------------------------------------------------------------
// Kernel 2: masked pairwise distances + exact top-K (smallest, jax tie order)
// via radix-select over u64 keys (float_bits(D_adjust)<<32 | j).
// One block per (b,i) row. 256 threads, 8 keys each (in registers).
// (R1 version, unchanged.)
// ---------------------------------------------------------------------------
__global__ __launch_bounds__(256) void knn_kernel(const float* __restrict__ mask,
                                                  float* __restrict__ outIdx,
                                                  float* __restrict__ outD) {
    __shared__ float Dsm[Nq];
    __shared__ unsigned int hist[256];
    __shared__ float warpred[8];
    __shared__ float s_Dmax;
    __shared__ int s_digit;
    __shared__ int s_rank;
    __shared__ unsigned long long cand[Kq];
    __shared__ int s_cnt;

    int row = blockIdx.x;
    int b = row / Nq;
    int tid = threadIdx.x;
    int lane = tid & 31, warp = tid >> 5;

    float4 xi = g_X[row];
    float mi = mask[row];
    const float* mrow = mask + b * Nq;

    // Pass 1: distances + row max
    float lmax = 0.f;
#pragma unroll
    for (int q = 0; q < Nq / 256; q++) {
        int j = tid + q * 256;
        float4 xj = g_X[b * Nq + j];
        float dx = xi.x - xj.x, dy = xi.y - xj.y, dz = xi.z - xj.z;
        float d = mi * mrow[j] * sqrtf(dx * dx + dy * dy + dz * dz + 1e-6f);
        Dsm[j] = d;
        lmax = fmaxf(lmax, d);
    }
    for (int o = 16; o; o >>= 1) lmax = fmaxf(lmax, __shfl_xor_sync(~0u, lmax, o));
    if (lane == 0) warpred[warp] = lmax;
    __syncthreads();
    if (tid == 0) {
        float m = warpred[0];
#pragma unroll
        for (int w = 1; w < 8; w++) m = fmaxf(m, warpred[w]);
        s_Dmax = m;
        s_rank = Kq;
        s_cnt = 0;
    }
    __syncthreads();
    float Dmax = s_Dmax;

    // Pass 2: build u64 keys in registers (D_adjust bits << 32 | index)
    unsigned long long kreg[Nq / 256];
#pragma unroll
    for (int q = 0; q < Nq / 256; q++) {
        int j = tid + q * 256;
        float m2 = mi * mrow[j];
        float adj = Dsm[j] + (1.f - m2) * Dmax;
        kreg[q] = ((unsigned long long)__float_as_uint(adj) << 32) | (unsigned)j;
    }

    // Radix select: find the Kq-th smallest key exactly.
    // Digits: bits [63:56],[55:48],[47:40],[39:32],[15:8],[7:0]
    unsigned long long prefix = 0, pmask = 0;
    const int shifts[6] = {56, 48, 40, 32, 8, 0};
#pragma unroll 1
    for (int r = 0; r < 6; r++) {
        int sh = shifts[r];
        hist[tid] = 0;
        __syncthreads();
#pragma unroll
        for (int q = 0; q < Nq / 256; q++)
            if ((kreg[q] & pmask) == prefix)
                atomicAdd(&hist[(unsigned)(kreg[q] >> sh) & 255u], 1u);
        __syncthreads();
        if (tid < 32) {
            int base = tid * 8;
            unsigned cnts[8];
            unsigned p = 0;
#pragma unroll
            for (int q2 = 0; q2 < 8; q2++) { cnts[q2] = hist[base + q2]; p += cnts[q2]; }
            unsigned incl = p;
            for (int o = 1; o < 32; o <<= 1) {
                unsigned v = __shfl_up_sync(~0u, incl, o);
                if (tid >= o) incl += v;
            }
            unsigned excl = incl - p;
            int rk = s_rank;
            __syncwarp();
            if ((int)excl < rk && rk <= (int)incl) {
                int rr = rk - (int)excl;
#pragma unroll
                for (int q2 = 0; q2 < 8; q2++) {
                    if (rr <= (int)cnts[q2]) { s_digit = base + q2; s_rank = rr; break; }
                    rr -= (int)cnts[q2];
                }
            }
        }
        __syncthreads();
        prefix |= ((unsigned long long)s_digit) << sh;
        pmask |= 0xFFull << sh;
    }
    // prefix == exact Kq-th smallest key; gather all keys <= prefix (exactly Kq)
#pragma unroll
    for (int q = 0; q < Nq / 256; q++)
        if (kreg[q] <= prefix) {
            int pos = atomicAdd(&s_cnt, 1);
            if (pos < Kq) cand[pos] = kreg[q];
        }
    __syncthreads();
    if (tid < Kq) {
        unsigned long long k = cand[tid];
        int rk = 0;
#pragma unroll
        for (int s = 0; s < Kq; s++) rk += (cand[s] < k);
        int j = (int)(unsigned)(k & 0xFFFFFFFFull);
        outIdx[(size_t)row * Kq + rk] = (float)j;
        outD[(size_t)row * Kq + rk] = __uint_as_float((unsigned)(k >> 32));
    }
}

// ---------------------------------------------------------------------------
// Kernel 3: per-edge features -> output channels + LayerNorm.
// PE contribution comes from the precomputed LUT g_C (17 FMAs/channel instead
// of 33). One 128-thread block per (b,i); thread = output channel.
// ---------------------------------------------------------------------------
__global__ __launch_bounds__(128) void edge_kernel(
    const float* __restrict__ eidx, const float* __restrict__ dnb,
    const int* __restrict__ resi, const int* __restrict__ lig,
    const float* __restrict__ bonds,
    const float* __restrict__ edge_w,
    const float* __restrict__ ln_g, const float* __restrict__ ln_b,
    float* __restrict__ outE) {
    __shared__ __align__(16) float f[Kq][20];  // 16 rbf + tb + pad
    __shared__ int dsm[Kq];
    __shared__ float red[16][4][2];
    __shared__ float stats[16][2];

    int c = threadIdx.x;
    int lane = c & 31, warp = c >> 5;
    int row = blockIdx.x;
    int b = row / Nq, i = row % Nq;

    // weights for rbf features + bond feature
    float w[17];
#pragma unroll
    for (int t = 0; t < 16; t++) w[t] = edge_w[(16 + t) * EC + c];
    w[16] = edge_w[32 * EC + c];
    float gg = ln_g[c], bb = ln_b[c];

    int ri = resi[row];
    int li = lig[row];
    const float* brow = bonds + ((size_t)b * Nq + i) * Nq;

    // Build feature rows (threads 0..47, one edge each)
    if (c < Kq) {
        int k = c;
        int j = (int)eidx[(size_t)row * Kq + k];
        float dk = dnb[(size_t)row * Kq + k];
        // chain_labels all-zero in reference => E_chains == 1 always
        int d = ri - resi[b * Nq + j] + 32;
        dsm[k] = max(0, min(64, d));
#pragma unroll
        for (int m = 0; m < 16; m++) {
            float mu = 2.f + (20.f / 15.f) * (float)m;
            float x = (dk - mu) * 0.8f;  // 1/1.25
            f[k][m] = __expf(-x * x);
        }
        f[k][16] = (li | lig[b * Nq + j]) ? brow[j] : 0.f;
        f[k][17] = f[k][18] = f[k][19] = 0.f;
    }
    __syncthreads();

    for (int k0 = 0; k0 < Kq; k0 += 16) {
        float e[16];
#pragma unroll
        for (int kk = 0; kk < 16; kk++) {
            const float4* fp = (const float4*)f[k0 + kk];
            float acc = g_C[dsm[k0 + kk] * EC + c];  // PE lookup (L1-resident)
#pragma unroll
            for (int q = 0; q < 4; q++) {
                float4 v = fp[q];
                acc += v.x * w[4 * q] + v.y * w[4 * q + 1] + v.z * w[4 * q + 2] +
                       v.w * w[4 * q + 3];
            }
            acc += fp[4].x * w[16];  // bond feature
            e[kk] = acc;
        }
        // LN reductions: warp partials -> smem -> finalize
#pragma unroll
        for (int kk = 0; kk < 16; kk++) {
            float s = e[kk], s2 = e[kk] * e[kk];
            for (int o = 16; o; o >>= 1) {
                s += __shfl_xor_sync(~0u, s, o);
                s2 += __shfl_xor_sync(~0u, s2, o);
            }
            if (lane == 0) { red[kk][warp][0] = s; red[kk][warp][1] = s2; }
        }
        __syncthreads();
        if (c < 16) {
            float s = red[c][0][0] + red[c][1][0] + red[c][2][0] + red[c][3][0];
            float s2 = red[c][0][1] + red[c][1][1] + red[c][2][1] + red[c][3][1];
            float mean = s * (1.f / EC);
            float var = s2 * (1.f / EC) - mean * mean;
            stats[c][0] = mean;
            stats[c][1] = rsqrtf(var + 1e-5f);
        }
        __syncthreads();
        size_t baseo = ((size_t)row * Kq + k0) * EC + c;
#pragma unroll
        for (int kk = 0; kk < 16; kk++) {
            float mean = stats[kk][0], rstd = stats[kk][1];
            outE[baseo + (size_t)kk * EC] = (e[kk] - mean) * rstd * gg + bb;
        }
        __syncthreads();
    }
}

// ---------------------------------------------------------------------------
extern "C" void kernel_launch(void* const* d_in, const int* in_sizes, int n_in,
                              void* d_out, int out_size) {
    const float* coords = (const float*)d_in[0];
    const float* mask   = (const float*)d_in[1];
    const float* bonds  = (const float*)d_in[2];
    const float* pe_w   = (const float*)d_in[3];
    const float* pe_b   = (const float*)d_in[4];
    const float* edge_w = (const float*)d_in[5];
    const float* ln_g   = (const float*)d_in[6];
    const float* ln_b   = (const float*)d_in[7];
    const int* center   = (const int*)d_in[8];
    const int* resi     = (const int*)d_in[9];
    // d_in[10] = asym_id (unused: chain encoding disabled in reference)
    const int* lig      = (const int*)d_in[11];

    float* outE = (float*)d_out;
    size_t nE = (size_t)Bq * Nq * Kq * EC;        // 50,331,648
    float* outIdx = outE + nE;                    // E_idx as float
    float* outD = outIdx + (size_t)Bq * Nq * Kq;  // D_neighbors

    prep_c_kernel<<<66, 128>>>(pe_w, pe_b, edge_w);
    gather_x_kernel<<<(Bq * Nq + 255) / 256, 256>>>(coords, mask, center);
    knn_kernel<<<Bq * Nq, 256>>>(mask, outIdx, outD);
    edge_kernel<<<Bq * Nq, 128>>>(outIdx, outD, resi, lig, bonds, edge_w,
                                  ln_g, ln_b, outE);
}

// round 5
// speedup vs baseline: 2.5416x; 1.2323x over previous
#include <cuda_runtime.h>
#include <math.h>

#define Bq 4
#define Nq 2048
#define Kq 48
#define EC 128

// Scratch: gathered/masked token center coords, [B*N] as float4
__device__ float4 g_X[Bq * Nq];
// Precomputed positional-encoding contribution: C[d][c] for d in [0,65]
__device__ float g_C[66 * EC];

// ---------------------------------------------------------------------------
// Kernel 0: fold (one_hot(d) @ pe_w + pe_b) @ edge_w[0:16] into a 66x128 LUT
// ---------------------------------------------------------------------------
__global__ void prep_c_kernel(const float* __restrict__ pe_w,
                              const float* __restrict__ pe_b,
                              const float* __restrict__ edge_w) {
    int d = blockIdx.x;
    int c = threadIdx.x;
    float acc = 0.f;
#pragma unroll
    for (int t = 0; t < 16; t++)
        acc += (pe_w[d * 16 + t] + pe_b[t]) * edge_w[t * EC + c];
    g_C[d * EC + c] = acc;
}

// ---------------------------------------------------------------------------
// Kernel 1: gather center-atom coords, apply token mask
// ---------------------------------------------------------------------------
__global__ void gather_x_kernel(const float* __restrict__ coords,
                                const float* __restrict__ mask,
                                const int* __restrict__ center) {
    int t = blockIdx.x * blockDim.x + threadIdx.x;
    if (t >= Bq * Nq) return;
    int b = t / Nq;
    int c = center[t];
    float m = mask[t];
    const float* p = coords + ((size_t)b * Nq + c) * 3;
    g_X[t] = make_float4(p[0] * m, p[1] * m, p[2] * m, 0.f);
}

// ---------------------------------------------------------------------------
// Kernel 2: masked pairwise distances + exact top-K (smallest, jax tie order)
// via radix-select over u64 keys (float_bits(D_adjust)<<32 | j).
// One block per (b,i) row. 256 threads, 8 keys each (in registers).
// ---------------------------------------------------------------------------
__global__ __launch_bounds__(256) void knn_kernel(const float* __restrict__ mask,
                                                  float* __restrict__ outIdx,
                                                  float* __restrict__ outD) {
    __shared__ float Dsm[Nq];
    __shared__ unsigned int hist[256];
    __shared__ float warpred[8];
    __shared__ float s_Dmax;
    __shared__ int s_digit;
    __shared__ int s_rank;
    __shared__ unsigned long long cand[Kq];
    __shared__ int s_cnt;

    int row = blockIdx.x;
    int b = row / Nq;
    int tid = threadIdx.x;
    int lane = tid & 31, warp = tid >> 5;

    float4 xi = g_X[row];
    float mi = mask[row];
    const float* mrow = mask + b * Nq;

    // Pass 1: distances + row max
    float lmax = 0.f;
#pragma unroll
    for (int q = 0; q < Nq / 256; q++) {
        int j = tid + q * 256;
        float4 xj = g_X[b * Nq + j];
        float dx = xi.x - xj.x, dy = xi.y - xj.y, dz = xi.z - xj.z;
        float d = mi * mrow[j] * sqrtf(dx * dx + dy * dy + dz * dz + 1e-6f);
        Dsm[j] = d;
        lmax = fmaxf(lmax, d);
    }
    for (int o = 16; o; o >>= 1) lmax = fmaxf(lmax, __shfl_xor_sync(~0u, lmax, o));
    if (lane == 0) warpred[warp] = lmax;
    __syncthreads();
    if (tid == 0) {
        float m = warpred[0];
#pragma unroll
        for (int w = 1; w < 8; w++) m = fmaxf(m, warpred[w]);
        s_Dmax = m;
        s_rank = Kq;
        s_cnt = 0;
    }
    __syncthreads();
    float Dmax = s_Dmax;

    // Pass 2: build u64 keys in registers (D_adjust bits << 32 | index)
    unsigned long long kreg[Nq / 256];
#pragma unroll
    for (int q = 0; q < Nq / 256; q++) {
        int j = tid + q * 256;
        float m2 = mi * mrow[j];
        float adj = Dsm[j] + (1.f - m2) * Dmax;
        kreg[q] = ((unsigned long long)__float_as_uint(adj) << 32) | (unsigned)j;
    }

    // Radix select: find the Kq-th smallest key exactly.
    unsigned long long prefix = 0, pmask = 0;
    const int shifts[6] = {56, 48, 40, 32, 8, 0};
#pragma unroll 1
    for (int r = 0; r < 6; r++) {
        int sh = shifts[r];
        hist[tid] = 0;
        __syncthreads();
#pragma unroll
        for (int q = 0; q < Nq / 256; q++)
            if ((kreg[q] & pmask) == prefix)
                atomicAdd(&hist[(unsigned)(kreg[q] >> sh) & 255u], 1u);
        __syncthreads();
        if (tid < 32) {
            int base = tid * 8;
            unsigned cnts[8];
            unsigned p = 0;
#pragma unroll
            for (int q2 = 0; q2 < 8; q2++) { cnts[q2] = hist[base + q2]; p += cnts[q2]; }
            unsigned incl = p;
            for (int o = 1; o < 32; o <<= 1) {
                unsigned v = __shfl_up_sync(~0u, incl, o);
                if (tid >= o) incl += v;
            }
            unsigned excl = incl - p;
            int rk = s_rank;
            __syncwarp();
            if ((int)excl < rk && rk <= (int)incl) {
                int rr = rk - (int)excl;
#pragma unroll
                for (int q2 = 0; q2 < 8; q2++) {
                    if (rr <= (int)cnts[q2]) { s_digit = base + q2; s_rank = rr; break; }
                    rr -= (int)cnts[q2];
                }
            }
        }
        __syncthreads();
        prefix |= ((unsigned long long)s_digit) << sh;
        pmask |= 0xFFull << sh;
    }
#pragma unroll
    for (int q = 0; q < Nq / 256; q++)
        if (kreg[q] <= prefix) {
            int pos = atomicAdd(&s_cnt, 1);
            if (pos < Kq) cand[pos] = kreg[q];
        }
    __syncthreads();
    if (tid < Kq) {
        unsigned long long k = cand[tid];
        int rk = 0;
#pragma unroll
        for (int s = 0; s < Kq; s++) rk += (cand[s] < k);
        int j = (int)(unsigned)(k & 0xFFFFFFFFull);
        outIdx[(size_t)row * Kq + rk] = (float)j;
        outD[(size_t)row * Kq + rk] = __uint_as_float((unsigned)(k >> 32));
    }
}

// ---------------------------------------------------------------------------
// Kernel 3: per-edge features -> output channels + LayerNorm.
// 64 threads per (b,i); thread owns ADJACENT channel pair (2c, 2c+1).
// Halves broadcast-LDS and store wavefronts vs 128-thread version;
// scalar FMA only (no f32x2 -> no register blowup). LN in chunks of 8.
// ---------------------------------------------------------------------------
__global__ __launch_bounds__(64) void edge_kernel(
    const float* __restrict__ eidx, const float* __restrict__ dnb,
    const int* __restrict__ resi, const int* __restrict__ lig,
    const float* __restrict__ bonds,
    const float* __restrict__ edge_w,
    const float* __restrict__ ln_g, const float* __restrict__ ln_b,
    float* __restrict__ outE) {
    __shared__ __align__(16) float f[Kq][20];  // 16 rbf + tb + pad
    __shared__ int dsm[Kq];
    __shared__ float red[8][2][2];
    __shared__ float stats[8][2];

    int c = threadIdx.x;  // 0..63 -> channels (2c, 2c+1)
    int lane = c & 31, warp = c >> 5;
    int row = blockIdx.x;
    int b = row / Nq, i = row % Nq;

    // weight pairs for rbf features + bond feature (adjacent channels)
    float2 w[17];
#pragma unroll
    for (int t = 0; t < 16; t++)
        w[t] = *(const float2*)&edge_w[(16 + t) * EC + 2 * c];
    w[16] = *(const float2*)&edge_w[32 * EC + 2 * c];
    float2 gg = *(const float2*)&ln_g[2 * c];
    float2 bb = *(const float2*)&ln_b[2 * c];

    int ri = resi[row];
    int li = lig[row];
    const float* brow = bonds + ((size_t)b * Nq + i) * Nq;

    // Build feature rows (threads 0..47, one edge each)
    if (c < Kq) {
        int k = c;
        int j = (int)eidx[(size_t)row * Kq + k];
        float dk = dnb[(size_t)row * Kq + k];
        // chain_labels all-zero in reference => E_chains == 1 always
        int d = ri - resi[b * Nq + j] + 32;
        dsm[k] = max(0, min(64, d));
#pragma unroll
        for (int m = 0; m < 16; m++) {
            float mu = 2.f + (20.f / 15.f) * (float)m;
            float x = (dk - mu) * 0.8f;  // 1/1.25
            f[k][m] = __expf(-x * x);
        }
        f[k][16] = (li | lig[b * Nq + j]) ? brow[j] : 0.f;
        f[k][17] = f[k][18] = f[k][19] = 0.f;
    }
    __syncthreads();

#pragma unroll 1
    for (int k0 = 0; k0 < Kq; k0 += 8) {
        float2 e[8];
#pragma unroll
        for (int kk = 0; kk < 8; kk++) {
            const float4* fp = (const float4*)f[k0 + kk];
            float2 C = *(const float2*)&g_C[dsm[k0 + kk] * EC + 2 * c];
            float a0 = C.x, a1 = C.y;
#pragma unroll
            for (int q = 0; q < 4; q++) {
                float4 v = fp[q];
                a0 += v.x * w[4 * q].x + v.y * w[4 * q + 1].x +
                      v.z * w[4 * q + 2].x + v.w * w[4 * q + 3].x;
                a1 += v.x * w[4 * q].y + v.y * w[4 * q + 1].y +
                      v.z * w[4 * q + 2].y + v.w * w[4 * q + 3].y;
            }
            float tb = fp[4].x;
            a0 += tb * w[16].x;
            a1 += tb * w[16].y;
            e[kk] = make_float2(a0, a1);
        }
        // LN reductions: each thread contributes 2 channels
#pragma unroll
        for (int kk = 0; kk < 8; kk++) {
            float s = e[kk].x + e[kk].y;
            float s2 = e[kk].x * e[kk].x + e[kk].y * e[kk].y;
            for (int o = 16; o; o >>= 1) {
                s += __shfl_xor_sync(~0u, s, o);
                s2 += __shfl_xor_sync(~0u, s2, o);
            }
            if (lane == 0) { red[kk][warp][0] = s; red[kk][warp][1] = s2; }
        }
        __syncthreads();
        if (c < 8) {
            float s = red[c][0][0] + red[c][1][0];
            float s2 = red[c][0][1] + red[c][1][1];
            float mean = s * (1.f / EC);
            float var = s2 * (1.f / EC) - mean * mean;
            stats[c][0] = mean;
            stats[c][1] = rsqrtf(var + 1e-5f);
        }
        __syncthreads();
        size_t baseo = ((size_t)row * Kq + k0) * EC + 2 * c;
#pragma unroll
        for (int kk = 0; kk < 8; kk++) {
            float mean = stats[kk][0], rstd = stats[kk][1];
            float2 o2;
            o2.x = (e[kk].x - mean) * rstd * gg.x + bb.x;
            o2.y = (e[kk].y - mean) * rstd * gg.y + bb.y;
            *(float2*)&outE[baseo + (size_t)kk * EC] = o2;
        }
        __syncthreads();
    }
}

// ---------------------------------------------------------------------------
extern "C" void kernel_launch(void* const* d_in, const int* in_sizes, int n_in,
                              void* d_out, int out_size) {
    const float* coords = (const float*)d_in[0];
    const float* mask   = (const float*)d_in[1];
    const float* bonds  = (const float*)d_in[2];
    const float* pe_w   = (const float*)d_in[3];
    const float* pe_b   = (const float*)d_in[4];
    const float* edge_w = (const float*)d_in[5];
    const float* ln_g   = (const float*)d_in[6];
    const float* ln_b   = (const float*)d_in[7];
    const int* center   = (const int*)d_in[8];
    const int* resi     = (const int*)d_in[9];
    // d_in[10] = asym_id (unused: chain encoding disabled in reference)
    const int* lig      = (const int*)d_in[11];

    float* outE = (float*)d_out;
    size_t nE = (size_t)Bq * Nq * Kq * EC;        // 50,331,648
    float* outIdx = outE + nE;                    // E_idx as float
    float* outD = outIdx + (size_t)Bq * Nq * Kq;  // D_neighbors

    prep_c_kernel<<<66, 128>>>(pe_w, pe_b, edge_w);
    gather_x_kernel<<<(Bq * Nq + 255) / 256, 256>>>(coords, mask, center);
    knn_kernel<<<Bq * Nq, 256>>>(mask, outIdx, outD);
    edge_kernel<<<Bq * Nq, 64>>>(outIdx, outD, resi, lig, bonds, edge_w,
                                 ln_g, ln_b, outE);
}